// round 7
// baseline (speedup 1.0000x reference)
#include <cuda_runtime.h>
#include <math.h>
#include <stdint.h>

#define B_  8
#define C_  256
#define IC_ 128
#define NQ  4096     // 64*64
#define NKV 1024     // 32*32

// ---------------- scratch (no allocs allowed) ----------------
__device__ float s_rgbp[B_*C_*NQ];     // pooled rgb   [b][256][4096]
__device__ float s_evp [B_*C_*NQ];     // pooled event [b][256][4096]
__device__ float s_theta[B_*IC_*NQ];   // [b][128][4096]
__device__ float s_convg[B_*IC_*NQ];   // conv(g) full res
__device__ float s_convphi[B_*IC_*NQ]; // conv(phi) full res
__device__ float s_gx  [B_*NKV*IC_];   // pooled g, transposed [b][kv][128]
__device__ float s_phip[B_*IC_*NKV];   // pooled phi [b][128][1024]
__device__ float s_y   [B_*IC_*NQ];    // attention output [b][128][4096]
__device__ float s_wy  [B_*C_*NQ];     // W conv output [b][256][4096]
__device__ float s_bnsum[C_];
__device__ float s_bnsq [C_];

// ---------------- kernel 1: 2x2 maxpool (128x128 -> 64x64) ----------------
__global__ void pool_kernel(const float* __restrict__ in, float* __restrict__ out, int zero_bn)
{
    int idx = blockIdx.x * 256 + threadIdx.x;         // over B*C*4096
    if (zero_bn && blockIdx.x == 0 && threadIdx.x < C_) {
        s_bnsum[threadIdx.x] = 0.f;                   // FIX: zero BOTH accumulators
        s_bnsq [threadIdx.x] = 0.f;
    }
    int p = idx & 4095;
    int plane = idx >> 12;                            // b*C + c
    int i = p >> 6, j = p & 63;
    const float2* in2 = (const float2*)in + (size_t)plane * 8192;  // 128*128/2
    float2 a = in2[(2*i)   * 64 + j];
    float2 b = in2[(2*i+1) * 64 + j];
    out[idx] = fmaxf(fmaxf(a.x, a.y), fmaxf(b.x, b.y));
}

// ---------------- kernel 2: conv1x1 GEMM  out[b][o][n] = sum_c w[o][c] x[b][c][n] + bias[o]
// block tile: 64 O x 128 N, K chunk 32.  256 threads, 8Ox4N per thread.
template<bool DO_BN>
__global__ void __launch_bounds__(256) conv_gemm(
    const float* __restrict__ x, const float* __restrict__ w,
    const float* __restrict__ bias, float* __restrict__ out, int C)
{
    __shared__ float a_s[32][68];     // [k][o]
    __shared__ float x_s[32][128];    // [k][n]
    const int t = threadIdx.x;
    const int warp = t >> 5, lane = t & 31;
    const int to = warp * 8;
    const int tn = lane * 4;
    const int n0 = blockIdx.x * 128;
    const int o0 = blockIdx.y * 64;
    const int Ototal = gridDim.y * 64;
    const float* xb = x + (size_t)blockIdx.z * C * NQ + n0;
    const float* wb = w + (size_t)o0 * C;

    float acc[8][4];
#pragma unroll
    for (int i = 0; i < 8; i++)
#pragma unroll
        for (int j = 0; j < 4; j++) acc[i][j] = 0.f;

    for (int k0 = 0; k0 < C; k0 += 32) {
        __syncthreads();
#pragma unroll
        for (int i = 0; i < 8; i++) {            // A tile 64x32
            int ii = t + i * 256;
            int o = ii >> 5, k = ii & 31;
            a_s[k][o] = wb[(size_t)o * C + k0 + k];
        }
#pragma unroll
        for (int i = 0; i < 4; i++) {            // X tile 32x128 (float4)
            int ii = t + i * 256;                // 1024 float4 slots
            int k = ii >> 5, n4 = (ii & 31) * 4;
            *(float4*)&x_s[k][n4] = *(const float4*)&xb[(size_t)(k0 + k) * NQ + n4];
        }
        __syncthreads();
#pragma unroll
        for (int k = 0; k < 32; k++) {
            float4 xv = *(float4*)&x_s[k][tn];
            float4 a0 = *(float4*)&a_s[k][to];
            float4 a1 = *(float4*)&a_s[k][to + 4];
            float ar[8] = {a0.x,a0.y,a0.z,a0.w,a1.x,a1.y,a1.z,a1.w};
            float xr[4] = {xv.x,xv.y,xv.z,xv.w};
#pragma unroll
            for (int oi = 0; oi < 8; oi++)
#pragma unroll
                for (int ni = 0; ni < 4; ni++)
                    acc[oi][ni] = fmaf(ar[oi], xr[ni], acc[oi][ni]);
        }
    }

    float* ob = out + (size_t)blockIdx.z * Ototal * NQ;
#pragma unroll
    for (int oi = 0; oi < 8; oi++) {
        int o = o0 + to + oi;
        float bv = bias[o];
        float4 v;
        v.x = acc[oi][0] + bv; v.y = acc[oi][1] + bv;
        v.z = acc[oi][2] + bv; v.w = acc[oi][3] + bv;
        *(float4*)&ob[(size_t)o * NQ + n0 + tn] = v;
        if (DO_BN) {
            float s = v.x + v.y + v.z + v.w;
            float q = v.x*v.x + v.y*v.y + v.z*v.z + v.w*v.w;
#pragma unroll
            for (int off = 16; off; off >>= 1) {
                s += __shfl_xor_sync(0xffffffffu, s, off);
                q += __shfl_xor_sync(0xffffffffu, q, off);
            }
            if (lane == 0) { atomicAdd(&s_bnsum[o], s); atomicAdd(&s_bnsq[o], q); }
        }
    }
}

// ---------------- kernel 3a: pool conv(g) 64x64->32x32 AND transpose to [b][kv][c]
__global__ void pool_g_kernel()
{
    __shared__ float ps[128][33];
    const int t = threadIdx.x;
    const int b = blockIdx.z;
    const int c0 = blockIdx.y * 32;
    const int kv0 = blockIdx.x * 128;
    const int c_off = t >> 7;       // 0..1
    const int p = t & 127;
    const int kv = kv0 + p;
    const int pr = kv >> 5, pc = kv & 31;
    const float2* base = (const float2*)s_convg + (size_t)b * IC_ * 2048;  // 4096 floats/plane
    for (int cc = 0; cc < 32; cc += 2) {
        int c = c0 + cc + c_off;
        const float2* pl = base + (size_t)c * 2048;
        float2 a = pl[(2*pr)   * 32 + pc];
        float2 d = pl[(2*pr+1) * 32 + pc];
        ps[p][cc + c_off] = fmaxf(fmaxf(a.x, a.y), fmaxf(d.x, d.y));
    }
    __syncthreads();
    float* outb = s_gx + (size_t)b * NKV * IC_;
#pragma unroll
    for (int i = 0; i < 16; i++) {
        int ii = t + i * 256;                 // 0..4095
        int pp = ii >> 5, c = ii & 31;
        outb[(size_t)(kv0 + pp) * IC_ + c0 + c] = ps[pp][c];
    }
}

// ---------------- kernel 3b: pool conv(phi) -> [b][c][1024]
__global__ void pool_phi_kernel()
{
    int idx = blockIdx.x * 256 + threadIdx.x;   // B*128*1024
    int kv = idx & 1023;
    int plane = idx >> 10;                      // b*128 + c
    int pr = kv >> 5, pc = kv & 31;
    const float2* pl = (const float2*)s_convphi + (size_t)plane * 2048;
    float2 a = pl[(2*pr)   * 32 + pc];
    float2 d = pl[(2*pr+1) * 32 + pc];
    s_phip[idx] = fmaxf(fmaxf(a.x, a.y), fmaxf(d.x, d.y));
}

// ---------------- kernel 4: fused flash attention ----------------
// block: 64 queries, one batch.  loop over 8 kv tiles of 128.
#define P_STRIDE 132
#define ATTN_SMEM_FLOATS (128*64 + 128*128 + 64*P_STRIDE + 256 + 256 + 64*3)

__global__ void __launch_bounds__(256) attn_kernel()
{
    extern __shared__ float sm[];
    float* th_s = sm;                   // [c][q] stride 64
    float* kv_s = th_s + 128 * 64;      // phi [c][k]128 then g [k][c]128
    float* p_s  = kv_s + 128 * 128;     // S/P  [q][k] stride 132
    float* redm = p_s + 64 * P_STRIDE;  // [4][64]
    float* redl = redm + 256;           // [4][64]
    float* mrow = redl + 256;           // [64]
    float* lrow = mrow + 64;
    float* srow = lrow + 64;

    const int t = threadIdx.x;
    const int warp = t >> 5, lane = t & 31;
    const int b = blockIdx.y;
    const int q0 = blockIdx.x * 64;
    const int tq8 = warp * 8;
    const int tk4 = lane * 4;    // k micro (QK)
    const int tc4 = lane * 4;    // c micro (PV)

    const float* theta_b = s_theta + (size_t)b * IC_ * NQ;
    const float* phi_b   = s_phip  + (size_t)b * IC_ * NKV;
    const float* g_b     = s_gx    + (size_t)b * NKV * IC_;

    // load theta tile [c][q]
#pragma unroll
    for (int i = 0; i < 8; i++) {
        int ii = t + i * 256;              // 2048 float4
        int c = ii >> 4, q4 = (ii & 15) * 4;
        *(float4*)&th_s[c * 64 + q4] = *(const float4*)&theta_b[(size_t)c * NQ + q0 + q4];
    }
    if (t < 64) { mrow[t] = -3.0e38f; lrow[t] = 0.f; }

    float y_acc[8][4];
#pragma unroll
    for (int i = 0; i < 8; i++)
#pragma unroll
        for (int j = 0; j < 4; j++) y_acc[i][j] = 0.f;

    for (int kt = 0; kt < NKV; kt += 128) {
        __syncthreads();                                     // (1)
        // load phi tile [c][k]
#pragma unroll
        for (int i = 0; i < 16; i++) {
            int ii = t + i * 256;                            // 4096 float4
            int c = ii >> 5, k4 = (ii & 31) * 4;
            *(float4*)&kv_s[c * 128 + k4] = *(const float4*)&phi_b[(size_t)c * NKV + kt + k4];
        }
        __syncthreads();                                     // (2)

        // QK: S[q][k] = sum_c theta[c][q] * phi[c][k]
        float s_acc[8][4];
#pragma unroll
        for (int i = 0; i < 8; i++)
#pragma unroll
            for (int j = 0; j < 4; j++) s_acc[i][j] = 0.f;
#pragma unroll 4
        for (int c = 0; c < 128; c++) {
            float4 pv = *(float4*)&kv_s[c * 128 + tk4];
            float4 t0 = *(float4*)&th_s[c * 64 + tq8];
            float4 t1 = *(float4*)&th_s[c * 64 + tq8 + 4];
            float tr[8] = {t0.x,t0.y,t0.z,t0.w,t1.x,t1.y,t1.z,t1.w};
            float pr[4] = {pv.x,pv.y,pv.z,pv.w};
#pragma unroll
            for (int qi = 0; qi < 8; qi++)
#pragma unroll
                for (int ki = 0; ki < 4; ki++)
                    s_acc[qi][ki] = fmaf(tr[qi], pr[ki], s_acc[qi][ki]);
        }
        // store S -> p_s [q][k] (conflict-free float4)
#pragma unroll
        for (int qi = 0; qi < 8; qi++) {
            float4 v = make_float4(s_acc[qi][0], s_acc[qi][1], s_acc[qi][2], s_acc[qi][3]);
            *(float4*)&p_s[(tq8 + qi) * P_STRIDE + tk4] = v;
        }
        __syncthreads();                                     // (3) S visible, kv_s free

        // load g tile [k][c] into kv_s
#pragma unroll
        for (int i = 0; i < 16; i++) {
            int ii = t + i * 256;
            int k = ii >> 5, c4 = (ii & 31) * 4;
            *(float4*)&kv_s[k * 128 + c4] = *(const float4*)&g_b[(size_t)(kt + k) * IC_ + c4];
        }
        // partial max: 4 threads per q
        {
            int q = t & 63, grp = t >> 6;
            float m = -3.0e38f;
#pragma unroll
            for (int kk = 0; kk < 8; kk++) {
                float4 v = *(float4*)&p_s[q * P_STRIDE + grp * 32 + kk * 4];
                m = fmaxf(m, fmaxf(fmaxf(v.x, v.y), fmaxf(v.z, v.w)));
            }
            redm[grp * 64 + q] = m;
        }
        __syncthreads();                                     // (4)
        if (t < 64) {
            float m = fmaxf(fmaxf(redm[t], redm[64 + t]), fmaxf(redm[128 + t], redm[192 + t]));
            float mo = mrow[t];
            float mn = fmaxf(mo, m);
            mrow[t] = mn;
            srow[t] = __expf(mo - mn);
        }
        __syncthreads();                                     // (5)
        // exp + partial sums
        {
            int q = t & 63, grp = t >> 6;
            float mn = mrow[q];
            float s = 0.f;
#pragma unroll
            for (int kk = 0; kk < 8; kk++) {
                float4 v = *(float4*)&p_s[q * P_STRIDE + grp * 32 + kk * 4];
                v.x = __expf(v.x - mn); v.y = __expf(v.y - mn);
                v.z = __expf(v.z - mn); v.w = __expf(v.w - mn);
                *(float4*)&p_s[q * P_STRIDE + grp * 32 + kk * 4] = v;
                s += v.x + v.y + v.z + v.w;
            }
            redl[grp * 64 + q] = s;
        }
        // rescale accumulator
#pragma unroll
        for (int qi = 0; qi < 8; qi++) {
            float sc = srow[tq8 + qi];
#pragma unroll
            for (int ci = 0; ci < 4; ci++) y_acc[qi][ci] *= sc;
        }
        __syncthreads();                                     // (6)
        if (t < 64)
            lrow[t] = lrow[t] * srow[t] + (redl[t] + redl[64 + t] + redl[128 + t] + redl[192 + t]);

        // PV: y[q][c] += sum_k P[q][k] * g[k][c]
#pragma unroll 2
        for (int k0 = 0; k0 < 128; k0 += 4) {
            float4 g0 = *(float4*)&kv_s[(k0 + 0) * 128 + tc4];
            float4 g1 = *(float4*)&kv_s[(k0 + 1) * 128 + tc4];
            float4 g2 = *(float4*)&kv_s[(k0 + 2) * 128 + tc4];
            float4 g3 = *(float4*)&kv_s[(k0 + 3) * 128 + tc4];
#pragma unroll
            for (int qi = 0; qi < 8; qi++) {
                float4 pq = *(float4*)&p_s[(tq8 + qi) * P_STRIDE + k0];
                y_acc[qi][0] = fmaf(pq.x, g0.x, y_acc[qi][0]);
                y_acc[qi][1] = fmaf(pq.x, g0.y, y_acc[qi][1]);
                y_acc[qi][2] = fmaf(pq.x, g0.z, y_acc[qi][2]);
                y_acc[qi][3] = fmaf(pq.x, g0.w, y_acc[qi][3]);
                y_acc[qi][0] = fmaf(pq.y, g1.x, y_acc[qi][0]);
                y_acc[qi][1] = fmaf(pq.y, g1.y, y_acc[qi][1]);
                y_acc[qi][2] = fmaf(pq.y, g1.z, y_acc[qi][2]);
                y_acc[qi][3] = fmaf(pq.y, g1.w, y_acc[qi][3]);
                y_acc[qi][0] = fmaf(pq.z, g2.x, y_acc[qi][0]);
                y_acc[qi][1] = fmaf(pq.z, g2.y, y_acc[qi][1]);
                y_acc[qi][2] = fmaf(pq.z, g2.z, y_acc[qi][2]);
                y_acc[qi][3] = fmaf(pq.z, g2.w, y_acc[qi][3]);
                y_acc[qi][0] = fmaf(pq.w, g3.x, y_acc[qi][0]);
                y_acc[qi][1] = fmaf(pq.w, g3.y, y_acc[qi][1]);
                y_acc[qi][2] = fmaf(pq.w, g3.z, y_acc[qi][2]);
                y_acc[qi][3] = fmaf(pq.w, g3.w, y_acc[qi][3]);
            }
        }
    }
    __syncthreads();
    // normalize and stage y as [c][q] in kv_s, then coalesced global write
#pragma unroll
    for (int qi = 0; qi < 8; qi++) {
        float inv = 1.0f / lrow[tq8 + qi];
#pragma unroll
        for (int ci = 0; ci < 4; ci++)
            kv_s[(tc4 + ci) * 64 + tq8 + qi] = y_acc[qi][ci] * inv;
    }
    __syncthreads();
    float* yb = s_y + (size_t)b * IC_ * NQ;
#pragma unroll
    for (int i = 0; i < 8; i++) {
        int ii = t + i * 256;               // 2048 float4
        int c = ii >> 4, q4 = (ii & 15) * 4;
        *(float4*)&yb[(size_t)c * NQ + q0 + q4] = *(float4*)&kv_s[c * 64 + q4];
    }
}

// ---------------- kernel 6: BN + residual + 2x nearest upsample ----------------
__global__ void final_kernel(const float* __restrict__ gamma, const float* __restrict__ beta,
                             float* __restrict__ out)
{
    const int b = blockIdx.z, c = blockIdx.y;
    const int p = blockIdx.x * 256 + threadIdx.x;    // 0..4095
    const float invN = 1.0f / 32768.0f;              // B * 64 * 64
    float mean = s_bnsum[c] * invN;
    float var  = s_bnsq[c] * invN - mean * mean;
    float rs = rsqrtf(var + 1e-5f);
    float gm = gamma[c] * rs;
    float bt = beta[c] - mean * gm;
    int i = p >> 6, j = p & 63;
    size_t off = ((size_t)b * C_ + c) * NQ + p;
    float v = s_wy[off] * gm + bt + s_rgbp[off];
    float2 vv = make_float2(v, v);
    float2* o2 = (float2*)out + ((size_t)b * C_ + c) * 8192;   // 128*128/2 per plane
    o2[(2*i)   * 64 + j] = vv;
    o2[(2*i+1) * 64 + j] = vv;
}

// ---------------- launch ----------------
extern "C" void kernel_launch(void* const* d_in, const int* in_sizes, int n_in,
                              void* d_out, int out_size)
{
    const float* rgb     = (const float*)d_in[0];
    const float* event_  = (const float*)d_in[1];
    const float* g_w     = (const float*)d_in[2];
    const float* g_b     = (const float*)d_in[3];
    const float* theta_w = (const float*)d_in[4];
    const float* theta_b = (const float*)d_in[5];
    const float* phi_w   = (const float*)d_in[6];
    const float* phi_b   = (const float*)d_in[7];
    const float* W_w     = (const float*)d_in[8];
    const float* W_b     = (const float*)d_in[9];
    const float* gamma   = (const float*)d_in[10];
    const float* beta    = (const float*)d_in[11];
    float* out = (float*)d_out;

    float *p_rgbp, *p_evp, *p_theta, *p_convg, *p_convphi, *p_y, *p_wy;
    cudaGetSymbolAddress((void**)&p_rgbp,    s_rgbp);
    cudaGetSymbolAddress((void**)&p_evp,     s_evp);
    cudaGetSymbolAddress((void**)&p_theta,   s_theta);
    cudaGetSymbolAddress((void**)&p_convg,   s_convg);
    cudaGetSymbolAddress((void**)&p_convphi, s_convphi);
    cudaGetSymbolAddress((void**)&p_y,       s_y);
    cudaGetSymbolAddress((void**)&p_wy,      s_wy);

    const size_t attn_smem = ATTN_SMEM_FLOATS * sizeof(float);
    cudaFuncSetAttribute(attn_kernel, cudaFuncAttributeMaxDynamicSharedMemorySize, (int)attn_smem);

    // 1) maxpool both modalities (first launch also zeroes BN accumulators)
    pool_kernel<<<32768, 256>>>(rgb, p_rgbp, 1);
    pool_kernel<<<32768, 256>>>(event_, p_evp, 0);

    // 2) projections (conv1x1 GEMMs)
    conv_gemm<false><<<dim3(32, 2, B_), 256>>>(p_rgbp, theta_w, theta_b, p_theta,   C_);
    conv_gemm<false><<<dim3(32, 2, B_), 256>>>(p_evp,  g_w,     g_b,     p_convg,   C_);
    conv_gemm<false><<<dim3(32, 2, B_), 256>>>(p_evp,  phi_w,   phi_b,   p_convphi, C_);

    // 3) sub-sample pools (g transposed for PV layout)
    pool_g_kernel<<<dim3(8, 4, B_), 256>>>();
    pool_phi_kernel<<<4096, 256>>>();

    // 4) fused attention (QK^T -> softmax -> PV)
    attn_kernel<<<dim3(64, B_), 256, attn_smem>>>();

    // 5) output conv + fused BN statistics
    conv_gemm<true><<<dim3(32, 4, B_), 256>>>(p_y, W_w, W_b, p_wy, IC_);

    // 6) BN normalize + residual + 2x upsample
    final_kernel<<<dim3(16, C_, B_), 256>>>(gamma, beta, out);
}